// round 1
// baseline (speedup 1.0000x reference)
#include <cuda_runtime.h>
#include <cstdint>

#define NFACE 1024
#define NB 2

// Preprocessed per-face records (7 x float4) + dilated bboxes.
// __device__ globals: allowed scratch (no allocations).
__device__ float4 g_face[NB * NFACE * 7];
__device__ float4 g_bbox[NB * NFACE];

// Constants from the reference
// SIGMA=1e-5, GAMMA=1e-4, EPS=1e-3, NEAR=1, FAR=100, DIST_EPS=1e-4, BG=0, FILL_BACK=true
#define F_EPS   1e-3f
#define K2      14426.950408889634f     /* log2(e)/GAMMA */
#define CSIG    144269.50408889634f     /* log2(e)/SIGMA */
#define THR     9.2102404e-05f          /* SIGMA*ln(1/DIST_EPS - 1) */
#define BB_PAD  0.0096f                 /* >= sqrt(THR), conservative */

__device__ __forceinline__ float fexp2(float x) {
    float y; asm("ex2.approx.ftz.f32 %0, %1;" : "=f"(y) : "f"(x)); return y;
}
__device__ __forceinline__ float frcp(float x) {
    float y; asm("rcp.approx.ftz.f32 %0, %1;" : "=f"(y) : "f"(x)); return y;
}
// One Newton step: needed where result feeds exp(./GAMMA) (1e4 error amplification)
__device__ __forceinline__ float frcp_nr(float x) {
    float r = frcp(x);
    return r * (2.0f - x * r);
}

// ---------------------------------------------------------------------------
// Kernel 1: per-face preprocessing. 2048 faces total.
// Record layout (7 float4):
//  r0: x0 y0 x1 y1
//  r1: x2 y2 a1 b1         (a1=e2y/det, b1=e2x/det)
//  r2: a2 b2 iL01 iL12     (a2=e1x/det, b2=e1y/det)
//  r3: iL20 iz0 iz1 iz2
//  r4: t00 t01 t02 t10     (tex[v][c], v-major)
//  r5: t11 t12 t20 t21
//  r6: t22 -- -- --
// bbox: xmin ymin xmax ymax (dilated by BB_PAD)
// ---------------------------------------------------------------------------
__global__ void prep_kernel(const float* __restrict__ fv,
                            const float* __restrict__ tex) {
    int i = blockIdx.x * blockDim.x + threadIdx.x;
    if (i >= NB * NFACE) return;
    const float* v = fv + i * 9;
    float x0 = v[0], y0 = v[1], z0 = v[2];
    float x1 = v[3], y1 = v[4], z1 = v[5];
    float x2 = v[6], y2 = v[7], z2 = v[8];

    float e1x = x1 - x0, e1y = y1 - y0;
    float e2x = x2 - x0, e2y = y2 - y0;
    float det = e1x * e2y - e1y * e2x;
    if (fabsf(det) < 1e-10f) det = 1e-10f;
    float inv = 1.0f / det;

    float e12x = x2 - x1, e12y = y2 - y1;
    float e20x = x0 - x2, e20y = y0 - y2;
    float iL01 = 1.0f / fmaxf(e1x * e1x + e1y * e1y, 1e-12f);
    float iL12 = 1.0f / fmaxf(e12x * e12x + e12y * e12y, 1e-12f);
    float iL20 = 1.0f / fmaxf(e20x * e20x + e20y * e20y, 1e-12f);

    const float* t = tex + i * 9;
    float4* fr = g_face + i * 7;
    fr[0] = make_float4(x0, y0, x1, y1);
    fr[1] = make_float4(x2, y2, e2y * inv, e2x * inv);
    fr[2] = make_float4(e1x * inv, e1y * inv, iL01, iL12);
    fr[3] = make_float4(iL20, 1.0f / z0, 1.0f / z1, 1.0f / z2);
    fr[4] = make_float4(t[0], t[1], t[2], t[3]);
    fr[5] = make_float4(t[4], t[5], t[6], t[7]);
    fr[6] = make_float4(t[8], 0.0f, 0.0f, 0.0f);

    float xmn = fminf(x0, fminf(x1, x2)) - BB_PAD;
    float xmx = fmaxf(x0, fmaxf(x1, x2)) + BB_PAD;
    float ymn = fminf(y0, fminf(y1, y2)) - BB_PAD;
    float ymx = fmaxf(y0, fmaxf(y1, y2)) + BB_PAD;
    g_bbox[i] = make_float4(xmn, ymn, xmx, ymx);
}

// ---------------------------------------------------------------------------
// Kernel 2: rasterize.
// Grid: NB*512 blocks (512 tiles of 8x4 px per batch), 256 threads (8 warps).
// Each warp: the same 32-pixel tile, its own 128 faces (online-softmax partials).
// End: combine 8 partials per pixel in smem, write 4 channels.
// ---------------------------------------------------------------------------
__global__ void __launch_bounds__(256)
raster_kernel(float* __restrict__ out) {
    __shared__ float red[6][8][32];   // [field][warp][pixel-lane]

    const int tid  = threadIdx.x;
    const int lane = tid & 31;
    const int wi   = tid >> 5;

    const int bidx  = blockIdx.x;
    const int batch = bidx >> 9;          // 512 tiles per batch
    const int tile  = bidx & 511;
    const int tx    = tile & 15;          // 16 tiles across (8 px wide)
    const int ty    = tile >> 4;          // 32 tiles down  (4 px tall)

    const int lx = lane & 7;
    const int ly = lane >> 3;
    const int w  = tx * 8 + lx;
    const int h  = ty * 4 + ly;

    const float px = (float)(2 * w + 1 - 128) * (1.0f / 128.0f);
    const float py = -(float)(2 * h + 1 - 128) * (1.0f / 128.0f);

    // Tile bounds (uniform across warp)
    const float txmin = (float)(2 * (tx * 8) + 1 - 128) * (1.0f / 128.0f);
    const float txmax = (float)(2 * (tx * 8 + 7) + 1 - 128) * (1.0f / 128.0f);
    const float tymax = -(float)(2 * (ty * 4) + 1 - 128) * (1.0f / 128.0f);
    const float tymin = -(float)(2 * (ty * 4 + 3) + 1 - 128) * (1.0f / 128.0f);

    // Online-softmax partial accumulators
    float m = F_EPS;
    float wsum = 0.0f, cr = 0.0f, cg = 0.0f, cb = 0.0f;
    float pa = 1.0f;  // prod(1 - Dmask)

    const float4* __restrict__ bb = g_bbox + batch * NFACE;
    const float4* __restrict__ fr = g_face + (size_t)batch * NFACE * 7;

    const int f0 = wi * (NFACE / 8);
    const int f1 = f0 + (NFACE / 8);

    for (int f = f0; f < f1; ++f) {
        // --- warp-uniform bbox cull (cheap path, ~96% of iterations) ---
        const float4 b = __ldg(bb + f);
        if (b.x > txmax || b.z < txmin || b.y > tymax || b.w < tymin) continue;

        const float4 r0 = __ldg(fr + f * 7 + 0);
        const float4 r1 = __ldg(fr + f * 7 + 1);
        const float4 r2 = __ldg(fr + f * 7 + 2);
        const float4 r3 = __ldg(fr + f * 7 + 3);

        const float x0 = r0.x, y0 = r0.y, x1 = r0.z, y1 = r0.w;
        const float x2 = r1.x, y2 = r1.y;

        const float dx = px - x0, dy = py - y0;
        const float w1 = dx * r1.z - dy * r1.w;
        const float w2 = dy * r2.x - dx * r2.y;
        const float w0 = 1.0f - w1 - w2;
        const bool inside = (w0 >= 0.0f) && (w1 >= 0.0f) && (w2 >= 0.0f);

        // segment (v0,v1)
        float ex = x1 - x0, ey = y1 - y0;
        float t  = __saturatef((dx * ex + dy * ey) * r2.z);
        float qx = dx - t * ex, qy = dy - t * ey;
        float dis = qx * qx + qy * qy;
        // segment (v1,v2)
        ex = x2 - x1; ey = y2 - y1;
        const float dx1 = px - x1, dy1 = py - y1;
        t  = __saturatef((dx1 * ex + dy1 * ey) * r2.w);
        qx = dx1 - t * ex; qy = dy1 - t * ey;
        dis = fminf(dis, qx * qx + qy * qy);
        // segment (v2,v0)
        ex = x0 - x2; ey = y0 - y2;
        const float dx2 = px - x2, dy2 = py - y2;
        t  = __saturatef((dx2 * ex + dy2 * ey) * r3.x);
        qx = dx2 - t * ex; qy = dy2 - t * ey;
        dis = fminf(dis, qx * qx + qy * qy);

        const bool near = inside || (dis <= THR);
        if (__all_sync(0xffffffffu, !near)) continue;

        // Dfrag = sigmoid(sign*dis/SIGMA)
        const float sarg = inside ? (-dis * CSIG) : (dis * CSIG);
        const float D = frcp(1.0f + fexp2(sarg));

        // alpha product: Dmask = near ? D : 0
        pa *= near ? (1.0f - D) : 1.0f;

        // normalized clipped barycentrics
        float c0 = __saturatef(w0), c1 = __saturatef(w1), c2 = __saturatef(w2);
        const float rs = frcp_nr(fmaxf(c0 + c1 + c2, 1e-5f));
        c0 *= rs; c1 *= rs; c2 *= rs;

        const float invz = c0 * r3.y + c1 * r3.z + c2 * r3.w;
        const float zp = frcp_nr(fmaxf(invz, 1e-8f));
        const bool valid = near && (zp >= 1.0f) && (zp <= 100.0f);

        if (__any_sync(0xffffffffu, valid)) {
            const float4 r4 = __ldg(fr + f * 7 + 4);
            const float4 r5 = __ldg(fr + f * 7 + 5);
            const float4 r6 = __ldg(fr + f * 7 + 6);

            const float zn = (100.0f - zp) * (1.0f / 99.0f);
            const float mnew = valid ? fmaxf(m, zn) : m;
            const float sc = fexp2((m - mnew) * K2);   // ==1 unless max updates
            wsum *= sc; cr *= sc; cg *= sc; cb *= sc;
            m = mnew;

            const float wgt = valid ? (D * fexp2((zn - m) * K2)) : 0.0f;
            wsum += wgt;
            const float w0n = wgt * c0, w1n = wgt * c1, w2n = wgt * c2;
            cr += w0n * r4.x + w1n * r4.w + w2n * r5.z;
            cg += w0n * r4.y + w1n * r5.x + w2n * r5.w;
            cb += w0n * r4.z + w1n * r5.y + w2n * r6.x;
        }
    }

    // stash partials
    red[0][wi][lane] = m;
    red[1][wi][lane] = wsum;
    red[2][wi][lane] = cr;
    red[3][wi][lane] = cg;
    red[4][wi][lane] = cb;
    red[5][wi][lane] = pa;
    __syncthreads();

    // combine the 8 face-subset partials per pixel; warp 0 handles all 32 pixels
    if (tid < 32) {
        float M = F_EPS;
        #pragma unroll
        for (int i = 0; i < 8; ++i) M = fmaxf(M, red[0][i][tid]);
        float ws = 0.0f, R = 0.0f, G = 0.0f, B = 0.0f, P = 1.0f;
        #pragma unroll
        for (int i = 0; i < 8; ++i) {
            const float sc = fexp2((red[0][i][tid] - M) * K2);
            ws += red[1][i][tid] * sc;
            R  += red[2][i][tid] * sc;
            G  += red[3][i][tid] * sc;
            B  += red[4][i][tid] * sc;
            P  *= red[5][i][tid];
        }
        const float wbg  = fexp2((F_EPS - M) * K2);
        const float invd = frcp_nr(ws + wbg);   // BG = 0 => rgb = colsum/denom

        const int plx = tid & 7, ply = tid >> 3;
        const int pw = tx * 8 + plx, ph = ty * 4 + ply;
        const int base = ((batch * 4) * 128 + ph) * 128 + pw;
        out[base + 0 * 128 * 128] = R * invd;
        out[base + 1 * 128 * 128] = G * invd;
        out[base + 2 * 128 * 128] = B * invd;
        out[base + 3 * 128 * 128] = 1.0f - P;
    }
}

// ---------------------------------------------------------------------------
extern "C" void kernel_launch(void* const* d_in, const int* in_sizes, int n_in,
                              void* d_out, int out_size) {
    const float* fv  = (const float*)d_in[0];   // [2,1024,3,3]
    const float* tex = (const float*)d_in[1];   // [2,1024,3,3]
    float* out = (float*)d_out;                 // [2,4,128,128]

    prep_kernel<<<(NB * NFACE + 127) / 128, 128>>>(fv, tex);
    raster_kernel<<<NB * 512, 256>>>(out);
}

// round 2
// speedup vs baseline: 3.4055x; 3.4055x over previous
#include <cuda_runtime.h>
#include <cstdint>

#define NFACE 1024
#define NB 2

// Preprocessed per-face records (7 x float4) + dilated bboxes.
__device__ float4 g_face[NB * NFACE * 7];
__device__ float4 g_bbox[NB * NFACE];

// Constants: SIGMA=1e-5, GAMMA=1e-4, EPS=1e-3, NEAR=1, FAR=100, DIST_EPS=1e-4
#define F_EPS   1e-3f
#define K2      14426.950408889634f     /* log2(e)/GAMMA */
#define CSIG    144269.50408889634f     /* log2(e)/SIGMA */
#define THR     9.2102404e-05f          /* SIGMA*ln(1/DIST_EPS - 1) */
#define BB_PAD  0.0096f                 /* >= sqrt(THR) */

__device__ __forceinline__ float fexp2(float x) {
    float y; asm("ex2.approx.ftz.f32 %0, %1;" : "=f"(y) : "f"(x)); return y;
}
__device__ __forceinline__ float frcp(float x) {
    float y; asm("rcp.approx.ftz.f32 %0, %1;" : "=f"(y) : "f"(x)); return y;
}
__device__ __forceinline__ float frcp_nr(float x) {
    float r = frcp(x);
    return r * (2.0f - x * r);
}

// ---------------------------------------------------------------------------
// Kernel 1: per-face preprocessing (record layout in comments of R1).
// ---------------------------------------------------------------------------
__global__ void prep_kernel(const float* __restrict__ fv,
                            const float* __restrict__ tex) {
    int i = blockIdx.x * blockDim.x + threadIdx.x;
    if (i >= NB * NFACE) return;
    const float* v = fv + i * 9;
    float x0 = v[0], y0 = v[1], z0 = v[2];
    float x1 = v[3], y1 = v[4], z1 = v[5];
    float x2 = v[6], y2 = v[7], z2 = v[8];

    float e1x = x1 - x0, e1y = y1 - y0;
    float e2x = x2 - x0, e2y = y2 - y0;
    float det = e1x * e2y - e1y * e2x;
    if (fabsf(det) < 1e-10f) det = 1e-10f;
    float inv = 1.0f / det;

    float e12x = x2 - x1, e12y = y2 - y1;
    float e20x = x0 - x2, e20y = y0 - y2;
    float iL01 = 1.0f / fmaxf(e1x * e1x + e1y * e1y, 1e-12f);
    float iL12 = 1.0f / fmaxf(e12x * e12x + e12y * e12y, 1e-12f);
    float iL20 = 1.0f / fmaxf(e20x * e20x + e20y * e20y, 1e-12f);

    const float* t = tex + i * 9;
    float4* fr = g_face + i * 7;
    fr[0] = make_float4(x0, y0, x1, y1);
    fr[1] = make_float4(x2, y2, e2y * inv, e2x * inv);
    fr[2] = make_float4(e1x * inv, e1y * inv, iL01, iL12);
    fr[3] = make_float4(iL20, 1.0f / z0, 1.0f / z1, 1.0f / z2);
    fr[4] = make_float4(t[0], t[1], t[2], t[3]);
    fr[5] = make_float4(t[4], t[5], t[6], t[7]);
    fr[6] = make_float4(t[8], 0.0f, 0.0f, 0.0f);

    float xmn = fminf(x0, fminf(x1, x2)) - BB_PAD;
    float xmx = fmaxf(x0, fmaxf(x1, x2)) + BB_PAD;
    float ymn = fminf(y0, fminf(y1, y2)) - BB_PAD;
    float ymx = fmaxf(y0, fmaxf(y1, y2)) + BB_PAD;
    g_bbox[i] = make_float4(xmn, ymn, xmx, ymx);
}

// ---------------------------------------------------------------------------
// Kernel 2: rasterize with in-block lane-parallel binning.
// Grid: NB*512 blocks (8x4 px tiles), 256 threads (8 warps).
// Phase 1: ballot-compact surviving faces into a flat smem list (deterministic).
// Phase 2: warps round-robin the flat list; online-softmax partials per pixel.
// Phase 3: combine 8 partials per pixel.
// ---------------------------------------------------------------------------
__global__ void __launch_bounds__(256)
raster_kernel(float* __restrict__ out) {
    __shared__ unsigned short seg[8][128];
    __shared__ unsigned short flat[NFACE];
    __shared__ int counts[8];
    __shared__ float red[6][8][32];   // [field][warp][pixel-lane]

    const int tid  = threadIdx.x;
    const int lane = tid & 31;
    const int wi   = tid >> 5;

    const int bidx  = blockIdx.x;
    const int batch = bidx >> 9;
    const int tile  = bidx & 511;
    const int tx    = tile & 15;          // 16 tiles across (8 px wide)
    const int ty    = tile >> 4;          // 32 tiles down  (4 px tall)

    const int lx = lane & 7;
    const int ly = lane >> 3;
    const float px = (float)(2 * (tx * 8 + lx) + 1 - 128) * (1.0f / 128.0f);
    const float py = -(float)(2 * (ty * 4 + ly) + 1 - 128) * (1.0f / 128.0f);

    const float txmin = (float)(2 * (tx * 8) + 1 - 128) * (1.0f / 128.0f);
    const float txmax = (float)(2 * (tx * 8 + 7) + 1 - 128) * (1.0f / 128.0f);
    const float tymax = -(float)(2 * (ty * 4) + 1 - 128) * (1.0f / 128.0f);
    const float tymin = -(float)(2 * (ty * 4 + 3) + 1 - 128) * (1.0f / 128.0f);

    const float4* __restrict__ bb = g_bbox + batch * NFACE;
    const float4* __restrict__ fr = g_face + (size_t)batch * NFACE * 7;

    // ---- Phase 1: lane-parallel bbox cull + deterministic compaction ----
    const int f0 = wi * 128;
    int cnt = 0;
    #pragma unroll
    for (int it = 0; it < 4; ++it) {
        const int f = f0 + it * 32 + lane;
        const float4 b = __ldg(bb + f);
        const bool hit = !(b.x > txmax || b.z < txmin || b.y > tymax || b.w < tymin);
        const unsigned msk = __ballot_sync(0xffffffffu, hit);
        if (hit) {
            const int pos = cnt + __popc(msk & ((1u << lane) - 1u));
            seg[wi][pos] = (unsigned short)f;
        }
        cnt += __popc(msk);
    }
    if (lane == 0) counts[wi] = cnt;
    __syncthreads();

    int base = 0, T = 0;
    #pragma unroll
    for (int i = 0; i < 8; ++i) {
        const int c = counts[i];
        if (i < wi) base += c;
        T += c;
    }
    for (int k = lane; k < cnt; k += 32) flat[base + k] = seg[wi][k];
    __syncthreads();

    // ---- Phase 2: full evaluation over flat list, round-robin per warp ----
    float m = F_EPS;
    float wsum = 0.0f, cr = 0.0f, cg = 0.0f, cb = 0.0f;
    float pa = 1.0f;

    for (int j = wi; j < T; j += 8) {
        const int f = flat[j];

        const float4 r0 = __ldg(fr + f * 7 + 0);
        const float4 r1 = __ldg(fr + f * 7 + 1);
        const float4 r2 = __ldg(fr + f * 7 + 2);
        const float4 r3 = __ldg(fr + f * 7 + 3);

        const float x0 = r0.x, y0 = r0.y, x1 = r0.z, y1 = r0.w;
        const float x2 = r1.x, y2 = r1.y;

        const float dx = px - x0, dy = py - y0;
        const float w1 = dx * r1.z - dy * r1.w;
        const float w2 = dy * r2.x - dx * r2.y;
        const float w0 = 1.0f - w1 - w2;
        const bool inside = (w0 >= 0.0f) && (w1 >= 0.0f) && (w2 >= 0.0f);

        float ex = x1 - x0, ey = y1 - y0;
        float t  = __saturatef((dx * ex + dy * ey) * r2.z);
        float qx = dx - t * ex, qy = dy - t * ey;
        float dis = qx * qx + qy * qy;

        ex = x2 - x1; ey = y2 - y1;
        const float dx1 = px - x1, dy1 = py - y1;
        t  = __saturatef((dx1 * ex + dy1 * ey) * r2.w);
        qx = dx1 - t * ex; qy = dy1 - t * ey;
        dis = fminf(dis, qx * qx + qy * qy);

        ex = x0 - x2; ey = y0 - y2;
        const float dx2 = px - x2, dy2 = py - y2;
        t  = __saturatef((dx2 * ex + dy2 * ey) * r3.x);
        qx = dx2 - t * ex; qy = dy2 - t * ey;
        dis = fminf(dis, qx * qx + qy * qy);

        const bool near = inside || (dis <= THR);
        if (__all_sync(0xffffffffu, !near)) continue;

        const float sarg = inside ? (-dis * CSIG) : (dis * CSIG);
        const float D = frcp(1.0f + fexp2(sarg));

        pa *= near ? (1.0f - D) : 1.0f;

        float c0 = __saturatef(w0), c1 = __saturatef(w1), c2 = __saturatef(w2);
        const float rs = frcp_nr(fmaxf(c0 + c1 + c2, 1e-5f));
        c0 *= rs; c1 *= rs; c2 *= rs;

        const float invz = c0 * r3.y + c1 * r3.z + c2 * r3.w;
        const float zp = frcp_nr(fmaxf(invz, 1e-8f));
        const bool valid = near && (zp >= 1.0f) && (zp <= 100.0f);

        if (__any_sync(0xffffffffu, valid)) {
            const float4 r4 = __ldg(fr + f * 7 + 4);
            const float4 r5 = __ldg(fr + f * 7 + 5);
            const float4 r6 = __ldg(fr + f * 7 + 6);

            const float zn = (100.0f - zp) * (1.0f / 99.0f);
            const float mnew = valid ? fmaxf(m, zn) : m;
            const float sc = fexp2((m - mnew) * K2);
            wsum *= sc; cr *= sc; cg *= sc; cb *= sc;
            m = mnew;

            const float wgt = valid ? (D * fexp2((zn - m) * K2)) : 0.0f;
            wsum += wgt;
            const float w0n = wgt * c0, w1n = wgt * c1, w2n = wgt * c2;
            cr += w0n * r4.x + w1n * r4.w + w2n * r5.z;
            cg += w0n * r4.y + w1n * r5.x + w2n * r5.w;
            cb += w0n * r4.z + w1n * r5.y + w2n * r6.x;
        }
    }

    red[0][wi][lane] = m;
    red[1][wi][lane] = wsum;
    red[2][wi][lane] = cr;
    red[3][wi][lane] = cg;
    red[4][wi][lane] = cb;
    red[5][wi][lane] = pa;
    __syncthreads();

    // ---- Phase 3: combine 8 partials per pixel (warp 0) ----
    if (tid < 32) {
        float M = F_EPS;
        #pragma unroll
        for (int i = 0; i < 8; ++i) M = fmaxf(M, red[0][i][tid]);
        float ws = 0.0f, R = 0.0f, G = 0.0f, B = 0.0f, P = 1.0f;
        #pragma unroll
        for (int i = 0; i < 8; ++i) {
            const float sc = fexp2((red[0][i][tid] - M) * K2);
            ws += red[1][i][tid] * sc;
            R  += red[2][i][tid] * sc;
            G  += red[3][i][tid] * sc;
            B  += red[4][i][tid] * sc;
            P  *= red[5][i][tid];
        }
        const float wbg  = fexp2((F_EPS - M) * K2);
        const float invd = frcp_nr(ws + wbg);

        const int plx = tid & 7, ply = tid >> 3;
        const int pw = tx * 8 + plx, ph = ty * 4 + ply;
        const int obase = ((batch * 4) * 128 + ph) * 128 + pw;
        out[obase + 0 * 128 * 128] = R * invd;
        out[obase + 1 * 128 * 128] = G * invd;
        out[obase + 2 * 128 * 128] = B * invd;
        out[obase + 3 * 128 * 128] = 1.0f - P;
    }
}

// ---------------------------------------------------------------------------
extern "C" void kernel_launch(void* const* d_in, const int* in_sizes, int n_in,
                              void* d_out, int out_size) {
    const float* fv  = (const float*)d_in[0];   // [2,1024,3,3]
    const float* tex = (const float*)d_in[1];   // [2,1024,3,3]
    float* out = (float*)d_out;                 // [2,4,128,128]

    prep_kernel<<<(NB * NFACE + 127) / 128, 128>>>(fv, tex);
    raster_kernel<<<NB * 512, 256>>>(out);
}

// round 3
// speedup vs baseline: 3.4311x; 1.0075x over previous
#include <cuda_runtime.h>
#include <cstdint>

#define NFACE 1024
#define NB 2
#define CHUNK 128

// Constants: SIGMA=1e-5, GAMMA=1e-4, EPS=1e-3, NEAR=1, FAR=100, DIST_EPS=1e-4
#define F_EPS   1e-3f
#define K2      14426.950408889634f     /* log2(e)/GAMMA */
#define CSIG    144269.50408889634f     /* log2(e)/SIGMA */
#define THR     9.2102404e-05f          /* SIGMA*ln(1/DIST_EPS - 1) */
#define BB_PAD  0.0096f                 /* >= sqrt(THR) */

__device__ __forceinline__ float fexp2(float x) {
    float y; asm("ex2.approx.ftz.f32 %0, %1;" : "=f"(y) : "f"(x)); return y;
}
__device__ __forceinline__ float frcp(float x) {
    float y; asm("rcp.approx.ftz.f32 %0, %1;" : "=f"(y) : "f"(x)); return y;
}
__device__ __forceinline__ float frcp_nr(float x) {
    float r = frcp(x);
    return r * (2.0f - x * r);
}

// ---------------------------------------------------------------------------
// Single fused kernel.
// Grid: NB*512 blocks (8x4 px tiles), 256 threads (8 warps).
// Phase 1 : lane-parallel bbox cull straight from face_vertices, ballot-compact
//           into a flat smem index list (deterministic order).
// Phase 1.5: for each chunk of <=128 listed faces, one thread per face builds
//           the full precomputed record (7 x float4) in smem (precise math).
// Phase 2 : warps round-robin the chunk; online-softmax partials per pixel.
// Phase 3 : combine the 8 per-warp partials per pixel; write 4 channels.
// Record layout (7 float4):
//  r0: x0 y0 x1 y1
//  r1: x2 y2 e2y/det e2x/det
//  r2: e1x/det e1y/det iL01 iL12
//  r3: iL20 iz0 iz1 iz2
//  r4: t00 t01 t02 t10   r5: t11 t12 t20 t21   r6: t22 - - -
// ---------------------------------------------------------------------------
__global__ void __launch_bounds__(256)
raster_fused(const float* __restrict__ fv_g,
             const float* __restrict__ tex_g,
             float* __restrict__ out) {
    __shared__ unsigned short seg[8][128];
    __shared__ unsigned short flat[NFACE];
    __shared__ int counts[8];
    __shared__ float4 recs[CHUNK][7];
    __shared__ float red[6][8][32];   // [field][warp][pixel-lane]

    const int tid  = threadIdx.x;
    const int lane = tid & 31;
    const int wi   = tid >> 5;

    const int bidx  = blockIdx.x;
    const int batch = bidx >> 9;
    const int tile  = bidx & 511;
    const int tx    = tile & 15;          // 16 tiles across (8 px wide)
    const int ty    = tile >> 4;          // 32 tiles down  (4 px tall)

    const int lx = lane & 7;
    const int ly = lane >> 3;
    const float px = (float)(2 * (tx * 8 + lx) + 1 - 128) * (1.0f / 128.0f);
    const float py = -(float)(2 * (ty * 4 + ly) + 1 - 128) * (1.0f / 128.0f);

    const float txmin = (float)(2 * (tx * 8) + 1 - 128) * (1.0f / 128.0f);
    const float txmax = (float)(2 * (tx * 8 + 7) + 1 - 128) * (1.0f / 128.0f);
    const float tymax = -(float)(2 * (ty * 4) + 1 - 128) * (1.0f / 128.0f);
    const float tymin = -(float)(2 * (ty * 4 + 3) + 1 - 128) * (1.0f / 128.0f);

    const float* __restrict__ fvb  = fv_g  + (size_t)batch * NFACE * 9;
    const float* __restrict__ texb = tex_g + (size_t)batch * NFACE * 9;

    // ---- Phase 1: bbox cull from raw vertices + deterministic compaction ----
    const int f0 = wi * 128;
    int cnt = 0;
    #pragma unroll
    for (int it = 0; it < 4; ++it) {
        const int f = f0 + it * 32 + lane;
        const float* v = fvb + f * 9;
        const float x0 = __ldg(v + 0), y0 = __ldg(v + 1);
        const float x1 = __ldg(v + 3), y1 = __ldg(v + 4);
        const float x2 = __ldg(v + 6), y2 = __ldg(v + 7);
        const float xmn = fminf(x0, fminf(x1, x2)) - BB_PAD;
        const float xmx = fmaxf(x0, fmaxf(x1, x2)) + BB_PAD;
        const float ymn = fminf(y0, fminf(y1, y2)) - BB_PAD;
        const float ymx = fmaxf(y0, fmaxf(y1, y2)) + BB_PAD;
        const bool hit = !(xmn > txmax || xmx < txmin || ymn > tymax || ymx < tymin);
        const unsigned msk = __ballot_sync(0xffffffffu, hit);
        if (hit) {
            const int pos = cnt + __popc(msk & ((1u << lane) - 1u));
            seg[wi][pos] = (unsigned short)f;
        }
        cnt += __popc(msk);
    }
    if (lane == 0) counts[wi] = cnt;
    __syncthreads();

    int base = 0, T = 0;
    #pragma unroll
    for (int i = 0; i < 8; ++i) {
        const int c = counts[i];
        if (i < wi) base += c;
        T += c;
    }
    for (int k = lane; k < cnt; k += 32) flat[base + k] = seg[wi][k];

    // Online-softmax partial accumulators (per pixel, per warp)
    float m = F_EPS;
    float wsum = 0.0f, cr = 0.0f, cg = 0.0f, cb = 0.0f;
    float pa = 1.0f;

    // ---- chunk loop ----
    for (int c0 = 0; c0 < T; c0 += CHUNK) {
        const int n = min(CHUNK, T - c0);
        __syncthreads();   // flat ready (1st iter) / prev-chunk eval done

        // Phase 1.5: build records for this chunk, one face per thread
        if (tid < n) {
            const int f = flat[c0 + tid];
            const float* v = fvb + f * 9;
            const float x0 = v[0], y0 = v[1], z0 = v[2];
            const float x1 = v[3], y1 = v[4], z1 = v[5];
            const float x2 = v[6], y2 = v[7], z2 = v[8];

            const float e1x = x1 - x0, e1y = y1 - y0;
            const float e2x = x2 - x0, e2y = y2 - y0;
            float det = e1x * e2y - e1y * e2x;
            if (fabsf(det) < 1e-10f) det = 1e-10f;
            const float inv = 1.0f / det;

            const float e12x = x2 - x1, e12y = y2 - y1;
            const float e20x = x0 - x2, e20y = y0 - y2;
            const float iL01 = 1.0f / fmaxf(e1x * e1x + e1y * e1y, 1e-12f);
            const float iL12 = 1.0f / fmaxf(e12x * e12x + e12y * e12y, 1e-12f);
            const float iL20 = 1.0f / fmaxf(e20x * e20x + e20y * e20y, 1e-12f);

            const float* t = texb + f * 9;
            recs[tid][0] = make_float4(x0, y0, x1, y1);
            recs[tid][1] = make_float4(x2, y2, e2y * inv, e2x * inv);
            recs[tid][2] = make_float4(e1x * inv, e1y * inv, iL01, iL12);
            recs[tid][3] = make_float4(iL20, 1.0f / z0, 1.0f / z1, 1.0f / z2);
            recs[tid][4] = make_float4(t[0], t[1], t[2], t[3]);
            recs[tid][5] = make_float4(t[4], t[5], t[6], t[7]);
            recs[tid][6] = make_float4(t[8], 0.0f, 0.0f, 0.0f);
        }
        __syncthreads();

        // Phase 2: evaluate chunk, warps round-robin
        #pragma unroll 2
        for (int j = wi; j < n; j += 8) {
            const float4 r0 = recs[j][0];
            const float4 r1 = recs[j][1];
            const float4 r2 = recs[j][2];
            const float4 r3 = recs[j][3];

            const float x0 = r0.x, y0 = r0.y, x1 = r0.z, y1 = r0.w;
            const float x2 = r1.x, y2 = r1.y;

            const float dx = px - x0, dy = py - y0;
            const float w1 = dx * r1.z - dy * r1.w;
            const float w2 = dy * r2.x - dx * r2.y;
            const float w0 = 1.0f - w1 - w2;
            const bool inside = (w0 >= 0.0f) && (w1 >= 0.0f) && (w2 >= 0.0f);

            float ex = x1 - x0, ey = y1 - y0;
            float t  = __saturatef((dx * ex + dy * ey) * r2.z);
            float qx = dx - t * ex, qy = dy - t * ey;
            float dis = qx * qx + qy * qy;

            ex = x2 - x1; ey = y2 - y1;
            const float dx1 = px - x1, dy1 = py - y1;
            t  = __saturatef((dx1 * ex + dy1 * ey) * r2.w);
            qx = dx1 - t * ex; qy = dy1 - t * ey;
            dis = fminf(dis, qx * qx + qy * qy);

            ex = x0 - x2; ey = y0 - y2;
            const float dx2 = px - x2, dy2 = py - y2;
            t  = __saturatef((dx2 * ex + dy2 * ey) * r3.x);
            qx = dx2 - t * ex; qy = dy2 - t * ey;
            dis = fminf(dis, qx * qx + qy * qy);

            const bool near = inside || (dis <= THR);
            if (__all_sync(0xffffffffu, !near)) continue;

            const float sarg = inside ? (-dis * CSIG) : (dis * CSIG);
            const float D = frcp(1.0f + fexp2(sarg));

            pa *= near ? (1.0f - D) : 1.0f;

            float c0c = __saturatef(w0), c1c = __saturatef(w1), c2c = __saturatef(w2);
            const float rs = frcp_nr(fmaxf(c0c + c1c + c2c, 1e-5f));
            c0c *= rs; c1c *= rs; c2c *= rs;

            const float invz = c0c * r3.y + c1c * r3.z + c2c * r3.w;
            const float zp = frcp_nr(fmaxf(invz, 1e-8f));
            const bool valid = near && (zp >= 1.0f) && (zp <= 100.0f);

            if (__any_sync(0xffffffffu, valid)) {
                const float4 r4 = recs[j][4];
                const float4 r5 = recs[j][5];
                const float4 r6 = recs[j][6];

                const float zn = (100.0f - zp) * (1.0f / 99.0f);
                const float mnew = valid ? fmaxf(m, zn) : m;
                const float sc = fexp2((m - mnew) * K2);
                wsum *= sc; cr *= sc; cg *= sc; cb *= sc;
                m = mnew;

                const float wgt = valid ? (D * fexp2((zn - m) * K2)) : 0.0f;
                wsum += wgt;
                const float w0n = wgt * c0c, w1n = wgt * c1c, w2n = wgt * c2c;
                cr += w0n * r4.x + w1n * r4.w + w2n * r5.z;
                cg += w0n * r4.y + w1n * r5.x + w2n * r5.w;
                cb += w0n * r4.z + w1n * r5.y + w2n * r6.x;
            }
        }
    }

    red[0][wi][lane] = m;
    red[1][wi][lane] = wsum;
    red[2][wi][lane] = cr;
    red[3][wi][lane] = cg;
    red[4][wi][lane] = cb;
    red[5][wi][lane] = pa;
    __syncthreads();

    // ---- Phase 3: combine 8 partials per pixel (warp 0) ----
    if (tid < 32) {
        float M = F_EPS;
        #pragma unroll
        for (int i = 0; i < 8; ++i) M = fmaxf(M, red[0][i][tid]);
        float ws = 0.0f, R = 0.0f, G = 0.0f, B = 0.0f, P = 1.0f;
        #pragma unroll
        for (int i = 0; i < 8; ++i) {
            const float sc = fexp2((red[0][i][tid] - M) * K2);
            ws += red[1][i][tid] * sc;
            R  += red[2][i][tid] * sc;
            G  += red[3][i][tid] * sc;
            B  += red[4][i][tid] * sc;
            P  *= red[5][i][tid];
        }
        const float wbg  = fexp2((F_EPS - M) * K2);
        const float invd = frcp_nr(ws + wbg);

        const int plx = tid & 7, ply = tid >> 3;
        const int pw = tx * 8 + plx, ph = ty * 4 + ply;
        const int obase = ((batch * 4) * 128 + ph) * 128 + pw;
        out[obase + 0 * 128 * 128] = R * invd;
        out[obase + 1 * 128 * 128] = G * invd;
        out[obase + 2 * 128 * 128] = B * invd;
        out[obase + 3 * 128 * 128] = 1.0f - P;
    }
}

// ---------------------------------------------------------------------------
extern "C" void kernel_launch(void* const* d_in, const int* in_sizes, int n_in,
                              void* d_out, int out_size) {
    const float* fv  = (const float*)d_in[0];   // [2,1024,3,3]
    const float* tex = (const float*)d_in[1];   // [2,1024,3,3]
    float* out = (float*)d_out;                 // [2,4,128,128]

    raster_fused<<<NB * 512, 256>>>(fv, tex, out);
}